// round 8
// baseline (speedup 1.0000x reference)
#include <cuda_runtime.h>
#include <cstdint>

// Instant-NGP fused forward, R8: tensor-core MLP, m16-half processing.
// Each warp owns 32 points; the MLP runs in two sequential m16 halves so the
// peak accumulator is 32 regs (not 64). smem per warp = sA[32x36] + sCh[16x68]
// = 8.96KB -> 35.8KB/CTA -> 6 CTAs/SM with an 85-reg cap. W1/W2/W3 read via
// __ldg (L1-hot). Warps fully decoupled (__syncwarp only).

constexpr int NLV = 16;
constexpr int TSZ = 1 << 19;
constexpr unsigned PRIME_Y = 2654435761u;

constexpr int SA_STR = 36;            // a-frag bank = (4g+q)%32, conflict-free
constexpr int SC_STR = 68;            // a-frag bank = (4g+q)%32, conflict-free
constexpr int WBLK   = 32 * SA_STR + 16 * SC_STR;   // 2240 floats / warp

__device__ __forceinline__ uint32_t f2tf(float f) {
    uint32_t u; asm("cvt.rna.tf32.f32 %0, %1;" : "=r"(u) : "f"(f)); return u;
}

__device__ __forceinline__ void mma8(float c[4], const uint32_t a[4], const uint32_t b[2]) {
    asm volatile("mma.sync.aligned.m16n8k8.row.col.f32.tf32.tf32.f32 "
                 "{%0,%1,%2,%3},{%4,%5,%6,%7},{%8,%9},{%0,%1,%2,%3};"
                 : "+f"(c[0]), "+f"(c[1]), "+f"(c[2]), "+f"(c[3])
                 : "r"(a[0]), "r"(a[1]), "r"(a[2]), "r"(a[3]), "r"(b[0]), "r"(b[1]));
}

__global__ __launch_bounds__(128, 6) void ngp_tc(
    const float* __restrict__ pos,      // [N,2]
    const float* __restrict__ table,    // [16, TSZ, 2]
    const float* __restrict__ W1,       // [32,64]
    const float* __restrict__ W2,       // [64,64]
    const float* __restrict__ W3,       // [64,3]
    float* __restrict__ out,            // [N,3]
    int n)
{
    __shared__ float sm[4 * WBLK];      // 35840 B

    const int t    = threadIdx.x;
    const int lane = t & 31;
    const int warp = t >> 5;
    const int g    = lane >> 2;             // groupID (0..7)
    const int q    = lane & 3;              // tid-in-group (0..3)
    const int base = blockIdx.x * 128;
    const int idx  = base + t;

    float* sA = sm + warp * WBLK;           // [32][36] feats
    float* sC = sA + 32 * SA_STR;           // [16][68] activations (one m-half)

    // ---- encode: feats -> sA[lane][0..31], 2 levels batched (8 loads in flight) ----
    {
        float2 p = (idx < n) ? ((const float2*)pos)[idx] : make_float2(0.f, 0.f);
#pragma unroll
        for (int lp = 0; lp < 8; lp++) {
            unsigned ix[2][4];
            float wgt[2][2];
#pragma unroll
            for (int l2 = 0; l2 < 2; l2++) {
                const int lvl = lp * 2 + l2;
                const int res = 16 << lvl;
                const float scale = (float)(res - 1);
                float px = p.x * scale + 0.5f;
                float py = p.y * scale + 0.5f;
                float fx = floorf(px), fy = floorf(py);
                wgt[l2][0] = px - fx;
                wgt[l2][1] = py - fy;
                unsigned cx = (unsigned)fx, cy = (unsigned)fy;
                if ((long long)res * res <= TSZ) {
                    unsigned i00 = cx + cy * (unsigned)res;
                    ix[l2][0] = i00;
                    ix[l2][1] = i00 + 1u;
                    ix[l2][2] = i00 + (unsigned)res;
                    ix[l2][3] = i00 + (unsigned)res + 1u;
                } else {
                    unsigned hy0 = cy * PRIME_Y;
                    unsigned hy1 = (cy + 1u) * PRIME_Y;
                    ix[l2][0] = (cx        ^ hy0) & (unsigned)(TSZ - 1);
                    ix[l2][1] = ((cx + 1u) ^ hy0) & (unsigned)(TSZ - 1);
                    ix[l2][2] = (cx        ^ hy1) & (unsigned)(TSZ - 1);
                    ix[l2][3] = ((cx + 1u) ^ hy1) & (unsigned)(TSZ - 1);
                }
            }
            float2 v[2][4];
#pragma unroll
            for (int l2 = 0; l2 < 2; l2++) {
                const float2* tl = (const float2*)table + (size_t)(lp * 2 + l2) * TSZ;
#pragma unroll
                for (int c = 0; c < 4; c++) v[l2][c] = __ldg(tl + ix[l2][c]);
            }
#pragma unroll
            for (int l2 = 0; l2 < 2; l2++) {
                const int lvl = lp * 2 + l2;
                float wx = wgt[l2][0], wy = wgt[l2][1];
                float w00 = (1.f - wx) * (1.f - wy);
                float w10 = wx * (1.f - wy);
                float w01 = (1.f - wx) * wy;
                float w11 = wx * wy;
                float f0 = w00 * v[l2][0].x + w10 * v[l2][1].x + w01 * v[l2][2].x + w11 * v[l2][3].x;
                float f1 = w00 * v[l2][0].y + w10 * v[l2][1].y + w01 * v[l2][2].y + w11 * v[l2][3].y;
                sA[lane * SA_STR + 2 * lvl + 0] = __uint_as_float(f2tf(f0));
                sA[lane * SA_STR + 2 * lvl + 1] = __uint_as_float(f2tf(f1));
            }
        }
    }
    __syncwarp();

    // ---- two m16 halves through the whole MLP ----
#pragma unroll
    for (int h = 0; h < 2; h++) {
        // -- GEMM1 half: C1[16x64] = A[16x32] @ W1[32x64] --
        float acc[8][4];
#pragma unroll
        for (int nt = 0; nt < 8; nt++)
#pragma unroll
            for (int r = 0; r < 4; r++) acc[nt][r] = 0.f;

#pragma unroll
        for (int k0 = 0; k0 < 32; k0 += 8) {
            uint32_t a[4];
            int lr = h * 16 + g;
            a[0] = __float_as_uint(sA[lr * SA_STR + k0 + q]);
            a[1] = __float_as_uint(sA[(lr + 8) * SA_STR + k0 + q]);
            a[2] = __float_as_uint(sA[lr * SA_STR + k0 + q + 4]);
            a[3] = __float_as_uint(sA[(lr + 8) * SA_STR + k0 + q + 4]);
#pragma unroll
            for (int nt = 0; nt < 8; nt++) {
                uint32_t b[2];
                b[0] = f2tf(__ldg(&W1[(k0 + q)     * 64 + nt * 8 + g]));
                b[1] = f2tf(__ldg(&W1[(k0 + q + 4) * 64 + nt * 8 + g]));
                mma8(acc[nt], a, b);
            }
        }
        __syncwarp();   // prior half's sC reads complete before overwrite

        // -- ReLU + store C1 half into sC (local rows 0..15) --
#pragma unroll
        for (int nt = 0; nt < 8; nt++) {
            int c = nt * 8 + 2 * q;
            sC[g * SC_STR + c]           = __uint_as_float(f2tf(fmaxf(acc[nt][0], 0.f)));
            sC[g * SC_STR + c + 1]       = __uint_as_float(f2tf(fmaxf(acc[nt][1], 0.f)));
            sC[(g + 8) * SC_STR + c]     = __uint_as_float(f2tf(fmaxf(acc[nt][2], 0.f)));
            sC[(g + 8) * SC_STR + c + 1] = __uint_as_float(f2tf(fmaxf(acc[nt][3], 0.f)));
        }
        __syncwarp();

        // -- GEMM2 half: C2[16x64] = C1[16x64] @ W2[64x64] --
        float acc2[8][4];
#pragma unroll
        for (int nt = 0; nt < 8; nt++)
#pragma unroll
            for (int r = 0; r < 4; r++) acc2[nt][r] = 0.f;

#pragma unroll
        for (int k0 = 0; k0 < 64; k0 += 8) {
            uint32_t a[4];
            a[0] = __float_as_uint(sC[g * SC_STR + k0 + q]);
            a[1] = __float_as_uint(sC[(g + 8) * SC_STR + k0 + q]);
            a[2] = __float_as_uint(sC[g * SC_STR + k0 + q + 4]);
            a[3] = __float_as_uint(sC[(g + 8) * SC_STR + k0 + q + 4]);
#pragma unroll
            for (int nt = 0; nt < 8; nt++) {
                uint32_t b[2];
                b[0] = f2tf(__ldg(&W2[(k0 + q)     * 64 + nt * 8 + g]));
                b[1] = f2tf(__ldg(&W2[(k0 + q + 4) * 64 + nt * 8 + g]));
                mma8(acc2[nt], a, b);
            }
        }

        // -- epilogue: ReLU + layer3 + quad reduce + store --
        float o[2][3];
#pragma unroll
        for (int hh = 0; hh < 2; hh++)
#pragma unroll
            for (int j = 0; j < 3; j++) o[hh][j] = 0.f;

#pragma unroll
        for (int nt = 0; nt < 8; nt++) {
            int c0 = nt * 8 + 2 * q;
            float w30[3], w31[3];
#pragma unroll
            for (int j = 0; j < 3; j++) {
                w30[j] = __ldg(&W3[c0 * 3 + j]);
                w31[j] = __ldg(&W3[(c0 + 1) * 3 + j]);
            }
            float v0 = fmaxf(acc2[nt][0], 0.f);
            float v1 = fmaxf(acc2[nt][1], 0.f);
            float v2 = fmaxf(acc2[nt][2], 0.f);
            float v3 = fmaxf(acc2[nt][3], 0.f);
#pragma unroll
            for (int j = 0; j < 3; j++) {
                o[0][j] += v0 * w30[j] + v1 * w31[j];
                o[1][j] += v2 * w30[j] + v3 * w31[j];
            }
        }

#pragma unroll
        for (int hh = 0; hh < 2; hh++)
#pragma unroll
            for (int j = 0; j < 3; j++) {
                float v = o[hh][j];
                v += __shfl_xor_sync(0xffffffffu, v, 1);
                v += __shfl_xor_sync(0xffffffffu, v, 2);
                o[hh][j] = v;
            }

        if (q < 3) {
            int j = q;
#pragma unroll
            for (int hh = 0; hh < 2; hh++) {
                int row = base + warp * 32 + h * 16 + g + hh * 8;
                if (row < n) out[row * 3 + j] = o[hh][j];
            }
        }
        __syncwarp();   // epilogue reads done before next half reuses sC
    }
}

extern "C" void kernel_launch(void* const* d_in, const int* in_sizes, int n_in,
                              void* d_out, int out_size) {
    const float* pos   = (const float*)d_in[0];
    const float* table = (const float*)d_in[1];
    const float* W1    = (const float*)d_in[2];
    const float* W2    = (const float*)d_in[3];
    const float* W3    = (const float*)d_in[4];
    float* out = (float*)d_out;
    int n = in_sizes[0] / 2;
    int blocks = (n + 127) / 128;
    ngp_tc<<<blocks, 128>>>(pos, table, W1, W2, W3, out, n);
}

// round 9
// speedup vs baseline: 1.7660x; 1.7660x over previous
#include <cuda_runtime.h>
#include <cstdint>

// Instant-NGP fused forward, R9: two-kernel split.
// Kernel A (encode): pure hash-grid gather, low-register, high-occupancy;
//   writes tf32-rounded feats to __device__ scratch in [tile32][feat][lane]
//   layout (all stores coalesced).
// Kernel B (MLP): R7's tensor-core GEMM path; feats copied linearly into
//   per-warp smem (sA aliases sC, warp-local syncs only), W2 staged in smem.

constexpr int NLV = 16;
constexpr int TSZ = 1 << 19;
constexpr unsigned PRIME_Y = 2654435761u;
constexpr int N_MAX = 4194304;

__device__ float g_feat[(size_t)N_MAX * 32];   // 512 MB scratch

__device__ __forceinline__ uint32_t f2tf(float f) {
    uint32_t u; asm("cvt.rna.tf32.f32 %0, %1;" : "=r"(u) : "f"(f)); return u;
}

__device__ __forceinline__ void mma8(float c[4], const uint32_t a[4], const uint32_t b[2]) {
    asm volatile("mma.sync.aligned.m16n8k8.row.col.f32.tf32.tf32.f32 "
                 "{%0,%1,%2,%3},{%4,%5,%6,%7},{%8,%9},{%0,%1,%2,%3};"
                 : "+f"(c[0]), "+f"(c[1]), "+f"(c[2]), "+f"(c[3])
                 : "r"(a[0]), "r"(a[1]), "r"(a[2]), "r"(a[3]), "r"(b[0]), "r"(b[1]));
}

// ======================= Kernel A: encode =======================
__global__ __launch_bounds__(256) void ngp_encode(
    const float* __restrict__ pos,      // [N,2]
    const float* __restrict__ table,    // [16, TSZ, 2]
    int n)
{
    const int idx  = blockIdx.x * 256 + threadIdx.x;
    if (idx >= n) return;
    const int lane = idx & 31;
    // scratch layout: tile = idx>>5; element (tile, feat c, lane) at tile*1024 + c*32 + lane
    float* dst = g_feat + ((size_t)(idx >> 5) << 10) + lane;

    const float2 p = ((const float2*)pos)[idx];

#pragma unroll
    for (int lp = 0; lp < 8; lp++) {
        unsigned ix[2][4];
        float wgt[2][2];
#pragma unroll
        for (int l2 = 0; l2 < 2; l2++) {
            const int lvl = lp * 2 + l2;
            const int res = 16 << lvl;
            const float scale = (float)(res - 1);
            float px = p.x * scale + 0.5f;
            float py = p.y * scale + 0.5f;
            float fx = floorf(px), fy = floorf(py);
            wgt[l2][0] = px - fx;
            wgt[l2][1] = py - fy;
            unsigned cx = (unsigned)fx, cy = (unsigned)fy;
            if ((long long)res * res <= TSZ) {
                unsigned i00 = cx + cy * (unsigned)res;
                ix[l2][0] = i00;
                ix[l2][1] = i00 + 1u;
                ix[l2][2] = i00 + (unsigned)res;
                ix[l2][3] = i00 + (unsigned)res + 1u;
            } else {
                unsigned hy0 = cy * PRIME_Y;
                unsigned hy1 = (cy + 1u) * PRIME_Y;
                ix[l2][0] = (cx        ^ hy0) & (unsigned)(TSZ - 1);
                ix[l2][1] = ((cx + 1u) ^ hy0) & (unsigned)(TSZ - 1);
                ix[l2][2] = (cx        ^ hy1) & (unsigned)(TSZ - 1);
                ix[l2][3] = ((cx + 1u) ^ hy1) & (unsigned)(TSZ - 1);
            }
        }
        float2 v[2][4];
#pragma unroll
        for (int l2 = 0; l2 < 2; l2++) {
            const float2* tl = (const float2*)table + (size_t)(lp * 2 + l2) * TSZ;
#pragma unroll
            for (int c = 0; c < 4; c++) v[l2][c] = __ldg(tl + ix[l2][c]);
        }
#pragma unroll
        for (int l2 = 0; l2 < 2; l2++) {
            const int lvl = lp * 2 + l2;
            float wx = wgt[l2][0], wy = wgt[l2][1];
            float w00 = (1.f - wx) * (1.f - wy);
            float w10 = wx * (1.f - wy);
            float w01 = (1.f - wx) * wy;
            float w11 = wx * wy;
            float f0 = w00 * v[l2][0].x + w10 * v[l2][1].x + w01 * v[l2][2].x + w11 * v[l2][3].x;
            float f1 = w00 * v[l2][0].y + w10 * v[l2][1].y + w01 * v[l2][2].y + w11 * v[l2][3].y;
            dst[(2 * lvl + 0) * 32] = __uint_as_float(f2tf(f0));   // coalesced
            dst[(2 * lvl + 1) * 32] = __uint_as_float(f2tf(f1));
        }
    }
}

// ======================= Kernel B: MLP =======================
constexpr int SA_STR = 33;            // sA[k][row], conflict-free a-frags
constexpr int SC_STR = 68;            // sC[row][col], conflict-free a-frags
constexpr int SW2_STR = 68;
constexpr int WBLK   = 32 * SC_STR;   // 2176 floats per warp block (sA aliases low part)
constexpr int SMEM_BYTES = (4 * WBLK + 64 * SW2_STR) * 4;   // 52224

__global__ __launch_bounds__(128, 4) void ngp_mlp(
    const float* __restrict__ W1,       // [32,64]
    const float* __restrict__ W2,       // [64,64]
    const float* __restrict__ W3,       // [64,3]
    float* __restrict__ out,            // [N,3]
    int n)
{
    extern __shared__ float sm[];
    float* sW2 = sm + 4 * WBLK;

    const int t    = threadIdx.x;
    const int lane = t & 31;
    const int warp = t >> 5;
    const int g    = lane >> 2;
    const int q    = lane & 3;
    const int base = blockIdx.x * 128;

    float* sW = sm + warp * WBLK;       // sA view: [k][row] stride 33 (first 1056 fl)
                                        // sC view: [row][col] stride 68

    // ---- stage W2 (tf32-rounded) ----
    for (int i = t; i < 64 * 64; i += 128) {
        int k = i >> 6, c = i & 63;
        sW2[k * SW2_STR + c] = __uint_as_float(f2tf(W2[i]));
    }

    // ---- copy feats: CTA's 4 tiles = 4096 contiguous floats in g_feat ----
    {
        const float4* src = (const float4*)(g_feat + ((size_t)(base >> 5) << 10));
        for (int i4 = t; i4 < 1024; i4 += 128) {
            float4 v = __ldg(src + i4);
            int i = i4 * 4;                       // linear float index
            int tile = i >> 10;
            int k = (i & 1023) >> 5;
            int r = i & 31;                       // r in {0,4,...,28}; same k for all 4
            float* d = sm + tile * WBLK + k * SA_STR + r;
            d[0] = v.x; d[1] = v.y; d[2] = v.z; d[3] = v.w;
        }
    }
    __syncthreads();

    // ---- GEMM1: C1[32x64] = A[32x32] @ W1[32x64] (warp-local tile) ----
    float acc[2][8][4];
#pragma unroll
    for (int mt = 0; mt < 2; mt++)
#pragma unroll
        for (int nt = 0; nt < 8; nt++)
#pragma unroll
            for (int r = 0; r < 4; r++) acc[mt][nt][r] = 0.f;

#pragma unroll
    for (int k0 = 0; k0 < 32; k0 += 8) {
        uint32_t a[2][4];
#pragma unroll
        for (int mt = 0; mt < 2; mt++) {
            int lr = mt * 16 + g;
            a[mt][0] = __float_as_uint(sW[(k0 + q) * SA_STR + lr]);
            a[mt][1] = __float_as_uint(sW[(k0 + q) * SA_STR + lr + 8]);
            a[mt][2] = __float_as_uint(sW[(k0 + q + 4) * SA_STR + lr]);
            a[mt][3] = __float_as_uint(sW[(k0 + q + 4) * SA_STR + lr + 8]);
        }
#pragma unroll
        for (int nt = 0; nt < 8; nt++) {
            uint32_t b[2];
            b[0] = f2tf(__ldg(&W1[(k0 + q)     * 64 + nt * 8 + g]));
            b[1] = f2tf(__ldg(&W1[(k0 + q + 4) * 64 + nt * 8 + g]));
            mma8(acc[0][nt], a[0], b);
            mma8(acc[1][nt], a[1], b);
        }
    }
    __syncwarp();   // warp-local: sA reads done before overwrite as sC

    // ---- ReLU + store C1 (tf32-rounded) into sC ----
#pragma unroll
    for (int mt = 0; mt < 2; mt++) {
        int lr = mt * 16 + g;
#pragma unroll
        for (int nt = 0; nt < 8; nt++) {
            int c = nt * 8 + 2 * q;
            sW[lr * SC_STR + c]           = __uint_as_float(f2tf(fmaxf(acc[mt][nt][0], 0.f)));
            sW[lr * SC_STR + c + 1]       = __uint_as_float(f2tf(fmaxf(acc[mt][nt][1], 0.f)));
            sW[(lr + 8) * SC_STR + c]     = __uint_as_float(f2tf(fmaxf(acc[mt][nt][2], 0.f)));
            sW[(lr + 8) * SC_STR + c + 1] = __uint_as_float(f2tf(fmaxf(acc[mt][nt][3], 0.f)));
        }
    }
    __syncwarp();

    // ---- GEMM2: C2[32x64] = C1[32x64] @ W2[64x64] (b-frags from smem) ----
    float acc2[2][8][4];
#pragma unroll
    for (int mt = 0; mt < 2; mt++)
#pragma unroll
        for (int nt = 0; nt < 8; nt++)
#pragma unroll
            for (int r = 0; r < 4; r++) acc2[mt][nt][r] = 0.f;

#pragma unroll
    for (int k0 = 0; k0 < 64; k0 += 8) {
        uint32_t a[2][4];
#pragma unroll
        for (int mt = 0; mt < 2; mt++) {
            int lr = mt * 16 + g;
            a[mt][0] = __float_as_uint(sW[lr * SC_STR + k0 + q]);
            a[mt][1] = __float_as_uint(sW[(lr + 8) * SC_STR + k0 + q]);
            a[mt][2] = __float_as_uint(sW[lr * SC_STR + k0 + q + 4]);
            a[mt][3] = __float_as_uint(sW[(lr + 8) * SC_STR + k0 + q + 4]);
        }
#pragma unroll
        for (int nt = 0; nt < 8; nt++) {
            uint32_t b[2];
            b[0] = __float_as_uint(sW2[(k0 + q)     * SW2_STR + nt * 8 + g]);
            b[1] = __float_as_uint(sW2[(k0 + q + 4) * SW2_STR + nt * 8 + g]);
            mma8(acc2[0][nt], a[0], b);
            mma8(acc2[1][nt], a[1], b);
        }
    }

    // ---- epilogue: ReLU + layer3 + quad reduce ----
    float o[2][2][3];
#pragma unroll
    for (int mt = 0; mt < 2; mt++)
#pragma unroll
        for (int h = 0; h < 2; h++)
#pragma unroll
            for (int j = 0; j < 3; j++) o[mt][h][j] = 0.f;

#pragma unroll
    for (int nt = 0; nt < 8; nt++) {
        int c0 = nt * 8 + 2 * q;
        float w30[3], w31[3];
#pragma unroll
        for (int j = 0; j < 3; j++) {
            w30[j] = __ldg(&W3[c0 * 3 + j]);
            w31[j] = __ldg(&W3[(c0 + 1) * 3 + j]);
        }
#pragma unroll
        for (int mt = 0; mt < 2; mt++) {
            float v0 = fmaxf(acc2[mt][nt][0], 0.f);
            float v1 = fmaxf(acc2[mt][nt][1], 0.f);
            float v2 = fmaxf(acc2[mt][nt][2], 0.f);
            float v3 = fmaxf(acc2[mt][nt][3], 0.f);
#pragma unroll
            for (int j = 0; j < 3; j++) {
                o[mt][0][j] += v0 * w30[j] + v1 * w31[j];
                o[mt][1][j] += v2 * w30[j] + v3 * w31[j];
            }
        }
    }

#pragma unroll
    for (int mt = 0; mt < 2; mt++)
#pragma unroll
        for (int h = 0; h < 2; h++)
#pragma unroll
            for (int j = 0; j < 3; j++) {
                float v = o[mt][h][j];
                v += __shfl_xor_sync(0xffffffffu, v, 1);
                v += __shfl_xor_sync(0xffffffffu, v, 2);
                o[mt][h][j] = v;
            }

    if (q < 3) {
        int j = q;
#pragma unroll
        for (int mt = 0; mt < 2; mt++)
#pragma unroll
            for (int h = 0; h < 2; h++) {
                int row = base + warp * 32 + mt * 16 + g + h * 8;
                if (row < n) out[row * 3 + j] = o[mt][h][j];
            }
    }
}

extern "C" void kernel_launch(void* const* d_in, const int* in_sizes, int n_in,
                              void* d_out, int out_size) {
    const float* pos   = (const float*)d_in[0];
    const float* table = (const float*)d_in[1];
    const float* W1    = (const float*)d_in[2];
    const float* W2    = (const float*)d_in[3];
    const float* W3    = (const float*)d_in[4];
    float* out = (float*)d_out;
    int n = in_sizes[0] / 2;

    static bool attr_set = false;
    if (!attr_set) {
        cudaFuncSetAttribute(ngp_mlp, cudaFuncAttributeMaxDynamicSharedMemorySize,
                             SMEM_BYTES);
        attr_set = true;
    }

    ngp_encode<<<(n + 255) / 256, 256>>>(pos, table, n);
    ngp_mlp<<<(n + 127) / 128, 128, SMEM_BYTES>>>(W1, W2, W3, out, n);
}

// round 10
// speedup vs baseline: 1.8126x; 1.0264x over previous
#include <cuda_runtime.h>
#include <cstdint>

// Instant-NGP fused forward, R10: two-kernel split (R9) + ldmatrix fragments.
// Kernel A (encode): unchanged from R9 (gather-bound, high-occupancy).
// Kernel B (MLP): GEMM2 fragments loaded with ldmatrix.m8n8.x4 (A from sC
// [row][k] stride 68; B from W2 staged TRANSPOSED [n][k] stride 68). Cuts
// 192 LDS.32 + address ALU per warp-tile to 48 LDSM.

constexpr int NLV = 16;
constexpr int TSZ = 1 << 19;
constexpr unsigned PRIME_Y = 2654435761u;
constexpr int N_MAX = 4194304;

__device__ float g_feat[(size_t)N_MAX * 32];   // 512 MB scratch

__device__ __forceinline__ uint32_t f2tf(float f) {
    uint32_t u; asm("cvt.rna.tf32.f32 %0, %1;" : "=r"(u) : "f"(f)); return u;
}

__device__ __forceinline__ void mma8(float c[4], const uint32_t a[4], const uint32_t b[2]) {
    asm volatile("mma.sync.aligned.m16n8k8.row.col.f32.tf32.tf32.f32 "
                 "{%0,%1,%2,%3},{%4,%5,%6,%7},{%8,%9},{%0,%1,%2,%3};"
                 : "+f"(c[0]), "+f"(c[1]), "+f"(c[2]), "+f"(c[3])
                 : "r"(a[0]), "r"(a[1]), "r"(a[2]), "r"(a[3]), "r"(b[0]), "r"(b[1]));
}

__device__ __forceinline__ void ldsm4(uint32_t r[4], uint32_t addr) {
    asm volatile("ldmatrix.sync.aligned.m8n8.x4.shared.b16 {%0,%1,%2,%3}, [%4];"
                 : "=r"(r[0]), "=r"(r[1]), "=r"(r[2]), "=r"(r[3]) : "r"(addr));
}

// ======================= Kernel A: encode (unchanged from R9) ===============
__global__ __launch_bounds__(256) void ngp_encode(
    const float* __restrict__ pos,      // [N,2]
    const float* __restrict__ table,    // [16, TSZ, 2]
    int n)
{
    const int idx  = blockIdx.x * 256 + threadIdx.x;
    if (idx >= n) return;
    const int lane = idx & 31;
    float* dst = g_feat + ((size_t)(idx >> 5) << 10) + lane;

    const float2 p = ((const float2*)pos)[idx];

#pragma unroll
    for (int lp = 0; lp < 8; lp++) {
        unsigned ix[2][4];
        float wgt[2][2];
#pragma unroll
        for (int l2 = 0; l2 < 2; l2++) {
            const int lvl = lp * 2 + l2;
            const int res = 16 << lvl;
            const float scale = (float)(res - 1);
            float px = p.x * scale + 0.5f;
            float py = p.y * scale + 0.5f;
            float fx = floorf(px), fy = floorf(py);
            wgt[l2][0] = px - fx;
            wgt[l2][1] = py - fy;
            unsigned cx = (unsigned)fx, cy = (unsigned)fy;
            if ((long long)res * res <= TSZ) {
                unsigned i00 = cx + cy * (unsigned)res;
                ix[l2][0] = i00;
                ix[l2][1] = i00 + 1u;
                ix[l2][2] = i00 + (unsigned)res;
                ix[l2][3] = i00 + (unsigned)res + 1u;
            } else {
                unsigned hy0 = cy * PRIME_Y;
                unsigned hy1 = (cy + 1u) * PRIME_Y;
                ix[l2][0] = (cx        ^ hy0) & (unsigned)(TSZ - 1);
                ix[l2][1] = ((cx + 1u) ^ hy0) & (unsigned)(TSZ - 1);
                ix[l2][2] = (cx        ^ hy1) & (unsigned)(TSZ - 1);
                ix[l2][3] = ((cx + 1u) ^ hy1) & (unsigned)(TSZ - 1);
            }
        }
        float2 v[2][4];
#pragma unroll
        for (int l2 = 0; l2 < 2; l2++) {
            const float2* tl = (const float2*)table + (size_t)(lp * 2 + l2) * TSZ;
#pragma unroll
            for (int c = 0; c < 4; c++) v[l2][c] = __ldg(tl + ix[l2][c]);
        }
#pragma unroll
        for (int l2 = 0; l2 < 2; l2++) {
            const int lvl = lp * 2 + l2;
            float wx = wgt[l2][0], wy = wgt[l2][1];
            float w00 = (1.f - wx) * (1.f - wy);
            float w10 = wx * (1.f - wy);
            float w01 = (1.f - wx) * wy;
            float w11 = wx * wy;
            float f0 = w00 * v[l2][0].x + w10 * v[l2][1].x + w01 * v[l2][2].x + w11 * v[l2][3].x;
            float f1 = w00 * v[l2][0].y + w10 * v[l2][1].y + w01 * v[l2][2].y + w11 * v[l2][3].y;
            dst[(2 * lvl + 0) * 32] = __uint_as_float(f2tf(f0));
            dst[(2 * lvl + 1) * 32] = __uint_as_float(f2tf(f1));
        }
    }
}

// ======================= Kernel B: MLP =======================
constexpr int SA_STR = 33;            // sA[k][row] (GEMM1 scalar a-frags)
constexpr int SC_STR = 68;            // sC[row][k], 272B rows (16B-aligned)
constexpr int SW2_STR = 68;           // W2T[n][k], 272B rows
constexpr int WBLK   = 32 * SC_STR;
constexpr int SMEM_BYTES = (4 * WBLK + 64 * SW2_STR) * 4;   // 52224

__global__ __launch_bounds__(128, 4) void ngp_mlp(
    const float* __restrict__ W1,       // [32,64]
    const float* __restrict__ W2,       // [64,64]
    const float* __restrict__ W3,       // [64,3]
    float* __restrict__ out,            // [N,3]
    int n)
{
    extern __shared__ float sm[];
    float* sW2T = sm + 4 * WBLK;        // [64 n][68], tf32-rounded, TRANSPOSED

    const int t    = threadIdx.x;
    const int lane = t & 31;
    const int warp = t >> 5;
    const int g    = lane >> 2;
    const int q    = lane & 3;
    const int base = blockIdx.x * 128;

    float* sW = sm + warp * WBLK;       // sA view: [k][row] stride 33; sC: [row][k] stride 68

    // ---- stage W2 TRANSPOSED (tf32-rounded): sW2T[n][k] = W2[k][n] ----
    for (int i = t; i < 64 * 64; i += 128) {
        int k = i >> 6, c = i & 63;
        sW2T[c * SW2_STR + k] = __uint_as_float(f2tf(W2[i]));
    }

    // ---- copy feats: CTA's 4 tiles = 4096 contiguous floats ----
    {
        const float4* src = (const float4*)(g_feat + ((size_t)(base >> 5) << 10));
        for (int i4 = t; i4 < 1024; i4 += 128) {
            float4 v = __ldg(src + i4);
            int i = i4 * 4;
            int tile = i >> 10;
            int k = (i & 1023) >> 5;
            int r = i & 31;
            float* d = sm + tile * WBLK + k * SA_STR + r;
            d[0] = v.x; d[1] = v.y; d[2] = v.z; d[3] = v.w;
        }
    }
    __syncthreads();

    // ---- GEMM1: C1[32x64] = A[32x32] @ W1[32x64] (scalar a-frags) ----
    float acc[2][8][4];
#pragma unroll
    for (int mt = 0; mt < 2; mt++)
#pragma unroll
        for (int nt = 0; nt < 8; nt++)
#pragma unroll
            for (int r = 0; r < 4; r++) acc[mt][nt][r] = 0.f;

#pragma unroll
    for (int k0 = 0; k0 < 32; k0 += 8) {
        uint32_t a[2][4];
#pragma unroll
        for (int mt = 0; mt < 2; mt++) {
            int lr = mt * 16 + g;
            a[mt][0] = __float_as_uint(sW[(k0 + q) * SA_STR + lr]);
            a[mt][1] = __float_as_uint(sW[(k0 + q) * SA_STR + lr + 8]);
            a[mt][2] = __float_as_uint(sW[(k0 + q + 4) * SA_STR + lr]);
            a[mt][3] = __float_as_uint(sW[(k0 + q + 4) * SA_STR + lr + 8]);
        }
#pragma unroll
        for (int nt = 0; nt < 8; nt++) {
            uint32_t b[2];
            b[0] = f2tf(__ldg(&W1[(k0 + q)     * 64 + nt * 8 + g]));
            b[1] = f2tf(__ldg(&W1[(k0 + q + 4) * 64 + nt * 8 + g]));
            mma8(acc[0][nt], a[0], b);
            mma8(acc[1][nt], a[1], b);
        }
    }
    __syncwarp();

    // ---- ReLU + store C1 (tf32-rounded) into sC [row][k] ----
#pragma unroll
    for (int mt = 0; mt < 2; mt++) {
        int lr = mt * 16 + g;
#pragma unroll
        for (int nt = 0; nt < 8; nt++) {
            int c = nt * 8 + 2 * q;
            sW[lr * SC_STR + c]           = __uint_as_float(f2tf(fmaxf(acc[mt][nt][0], 0.f)));
            sW[lr * SC_STR + c + 1]       = __uint_as_float(f2tf(fmaxf(acc[mt][nt][1], 0.f)));
            sW[(lr + 8) * SC_STR + c]     = __uint_as_float(f2tf(fmaxf(acc[mt][nt][2], 0.f)));
            sW[(lr + 8) * SC_STR + c + 1] = __uint_as_float(f2tf(fmaxf(acc[mt][nt][3], 0.f)));
        }
    }
    __syncwarp();

    // ---- GEMM2 via ldmatrix: C2[32x64] = C1[32x64] @ W2[64x64] ----
    float acc2[2][8][4];
#pragma unroll
    for (int mt = 0; mt < 2; mt++)
#pragma unroll
        for (int nt = 0; nt < 8; nt++)
#pragma unroll
            for (int r = 0; r < 4; r++) acc2[mt][nt][r] = 0.f;

    {
        const uint32_t sw_u32   = (uint32_t)__cvta_generic_to_shared(sW);
        const uint32_t sw2t_u32 = (uint32_t)__cvta_generic_to_shared(sW2T);
        const int m_ = lane >> 3;           // matrix index within x4 group
        const int r8 = lane & 7;
        // A: matrix m_: row = mt*16 + r8 + 8*(m_&1), kofs = 4*(m_>>1)
        uint32_t aaddr0 = sw_u32 + ((r8 + 8 * (m_ & 1)) * SC_STR + 4 * (m_ >> 1)) * 4;
        uint32_t aaddr1 = aaddr0 + 16 * SC_STR * 4;
        // B: matrix m_: n-row = nt0*8 + 8*(m_>>1) + r8, kofs = 4*(m_&1)
        uint32_t baddr  = sw2t_u32 + (((m_ >> 1) * 8 + r8) * SW2_STR + 4 * (m_ & 1)) * 4;

#pragma unroll
        for (int k0 = 0; k0 < 64; k0 += 8) {
            uint32_t a0r[4], a1r[4];
            ldsm4(a0r, aaddr0 + k0 * 4);
            ldsm4(a1r, aaddr1 + k0 * 4);
#pragma unroll
            for (int nt0 = 0; nt0 < 8; nt0 += 2) {
                uint32_t br[4];   // {b0(nt0), b1(nt0), b0(nt0+1), b1(nt0+1)}
                ldsm4(br, baddr + (nt0 * 8 * SW2_STR + k0) * 4);
                mma8(acc2[0][nt0],     a0r, &br[0]);
                mma8(acc2[1][nt0],     a1r, &br[0]);
                mma8(acc2[0][nt0 + 1], a0r, &br[2]);
                mma8(acc2[1][nt0 + 1], a1r, &br[2]);
            }
        }
    }

    // ---- epilogue: ReLU + layer3 + quad reduce ----
    float o[2][2][3];
#pragma unroll
    for (int mt = 0; mt < 2; mt++)
#pragma unroll
        for (int h = 0; h < 2; h++)
#pragma unroll
            for (int j = 0; j < 3; j++) o[mt][h][j] = 0.f;

#pragma unroll
    for (int nt = 0; nt < 8; nt++) {
        int c0 = nt * 8 + 2 * q;
        float w30[3], w31[3];
#pragma unroll
        for (int j = 0; j < 3; j++) {
            w30[j] = __ldg(&W3[c0 * 3 + j]);
            w31[j] = __ldg(&W3[(c0 + 1) * 3 + j]);
        }
#pragma unroll
        for (int mt = 0; mt < 2; mt++) {
            float v0 = fmaxf(acc2[mt][nt][0], 0.f);
            float v1 = fmaxf(acc2[mt][nt][1], 0.f);
            float v2 = fmaxf(acc2[mt][nt][2], 0.f);
            float v3 = fmaxf(acc2[mt][nt][3], 0.f);
#pragma unroll
            for (int j = 0; j < 3; j++) {
                o[mt][0][j] += v0 * w30[j] + v1 * w31[j];
                o[mt][1][j] += v2 * w30[j] + v3 * w31[j];
            }
        }
    }

#pragma unroll
    for (int mt = 0; mt < 2; mt++)
#pragma unroll
        for (int h = 0; h < 2; h++)
#pragma unroll
            for (int j = 0; j < 3; j++) {
                float v = o[mt][h][j];
                v += __shfl_xor_sync(0xffffffffu, v, 1);
                v += __shfl_xor_sync(0xffffffffu, v, 2);
                o[mt][h][j] = v;
            }

    if (q < 3) {
        int j = q;
#pragma unroll
        for (int mt = 0; mt < 2; mt++)
#pragma unroll
            for (int h = 0; h < 2; h++) {
                int row = base + warp * 32 + mt * 16 + g + h * 8;
                if (row < n) out[row * 3 + j] = o[mt][h][j];
            }
    }
}

extern "C" void kernel_launch(void* const* d_in, const int* in_sizes, int n_in,
                              void* d_out, int out_size) {
    const float* pos   = (const float*)d_in[0];
    const float* table = (const float*)d_in[1];
    const float* W1    = (const float*)d_in[2];
    const float* W2    = (const float*)d_in[3];
    const float* W3    = (const float*)d_in[4];
    float* out = (float*)d_out;
    int n = in_sizes[0] / 2;

    static bool attr_set = false;
    if (!attr_set) {
        cudaFuncSetAttribute(ngp_mlp, cudaFuncAttributeMaxDynamicSharedMemorySize,
                             SMEM_BYTES);
        attr_set = true;
    }

    ngp_encode<<<(n + 255) / 256, 256>>>(pos, table, n);
    ngp_mlp<<<(n + 127) / 128, 128, SMEM_BYTES>>>(W1, W2, W3, out, n);
}

// round 11
// speedup vs baseline: 2.1113x; 1.1648x over previous
#include <cuda_runtime.h>
#include <cstdint>

// Instant-NGP fused forward, R11: two-kernel split + tiled MLP.
// Kernel A (encode): unchanged (gather-bound).
// Kernel B (MLP): each CTA processes 512 points (4 warps x 4 tiles of 32).
// W2 staged (transposed, tf32) ONCE per CTA -> staging cost per point /4.
// Warp-local pipeline per tile: feat copy -> GEMM1 -> ReLU -> GEMM2(ldmatrix)
// -> layer3 epilogue. Only __syncwarp between phases.

constexpr int NLV = 16;
constexpr int TSZ = 1 << 19;
constexpr unsigned PRIME_Y = 2654435761u;
constexpr int N_MAX = 4194304;

__device__ float g_feat[(size_t)N_MAX * 32];   // 512 MB scratch

__device__ __forceinline__ uint32_t f2tf(float f) {
    uint32_t u; asm("cvt.rna.tf32.f32 %0, %1;" : "=r"(u) : "f"(f)); return u;
}

__device__ __forceinline__ void mma8(float c[4], const uint32_t a[4], const uint32_t b[2]) {
    asm volatile("mma.sync.aligned.m16n8k8.row.col.f32.tf32.tf32.f32 "
                 "{%0,%1,%2,%3},{%4,%5,%6,%7},{%8,%9},{%0,%1,%2,%3};"
                 : "+f"(c[0]), "+f"(c[1]), "+f"(c[2]), "+f"(c[3])
                 : "r"(a[0]), "r"(a[1]), "r"(a[2]), "r"(a[3]), "r"(b[0]), "r"(b[1]));
}

__device__ __forceinline__ void ldsm4(uint32_t r[4], uint32_t addr) {
    asm volatile("ldmatrix.sync.aligned.m8n8.x4.shared.b16 {%0,%1,%2,%3}, [%4];"
                 : "=r"(r[0]), "=r"(r[1]), "=r"(r[2]), "=r"(r[3]) : "r"(addr));
}

// ======================= Kernel A: encode (unchanged) ===============
__global__ __launch_bounds__(256) void ngp_encode(
    const float* __restrict__ pos,
    const float* __restrict__ table,
    int n)
{
    const int idx  = blockIdx.x * 256 + threadIdx.x;
    if (idx >= n) return;
    const int lane = idx & 31;
    float* dst = g_feat + ((size_t)(idx >> 5) << 10) + lane;

    const float2 p = ((const float2*)pos)[idx];

#pragma unroll
    for (int lp = 0; lp < 8; lp++) {
        unsigned ix[2][4];
        float wgt[2][2];
#pragma unroll
        for (int l2 = 0; l2 < 2; l2++) {
            const int lvl = lp * 2 + l2;
            const int res = 16 << lvl;
            const float scale = (float)(res - 1);
            float px = p.x * scale + 0.5f;
            float py = p.y * scale + 0.5f;
            float fx = floorf(px), fy = floorf(py);
            wgt[l2][0] = px - fx;
            wgt[l2][1] = py - fy;
            unsigned cx = (unsigned)fx, cy = (unsigned)fy;
            if ((long long)res * res <= TSZ) {
                unsigned i00 = cx + cy * (unsigned)res;
                ix[l2][0] = i00;
                ix[l2][1] = i00 + 1u;
                ix[l2][2] = i00 + (unsigned)res;
                ix[l2][3] = i00 + (unsigned)res + 1u;
            } else {
                unsigned hy0 = cy * PRIME_Y;
                unsigned hy1 = (cy + 1u) * PRIME_Y;
                ix[l2][0] = (cx        ^ hy0) & (unsigned)(TSZ - 1);
                ix[l2][1] = ((cx + 1u) ^ hy0) & (unsigned)(TSZ - 1);
                ix[l2][2] = (cx        ^ hy1) & (unsigned)(TSZ - 1);
                ix[l2][3] = ((cx + 1u) ^ hy1) & (unsigned)(TSZ - 1);
            }
        }
        float2 v[2][4];
#pragma unroll
        for (int l2 = 0; l2 < 2; l2++) {
            const float2* tl = (const float2*)table + (size_t)(lp * 2 + l2) * TSZ;
#pragma unroll
            for (int c = 0; c < 4; c++) v[l2][c] = __ldg(tl + ix[l2][c]);
        }
#pragma unroll
        for (int l2 = 0; l2 < 2; l2++) {
            const int lvl = lp * 2 + l2;
            float wx = wgt[l2][0], wy = wgt[l2][1];
            float w00 = (1.f - wx) * (1.f - wy);
            float w10 = wx * (1.f - wy);
            float w01 = (1.f - wx) * wy;
            float w11 = wx * wy;
            float f0 = w00 * v[l2][0].x + w10 * v[l2][1].x + w01 * v[l2][2].x + w11 * v[l2][3].x;
            float f1 = w00 * v[l2][0].y + w10 * v[l2][1].y + w01 * v[l2][2].y + w11 * v[l2][3].y;
            dst[(2 * lvl + 0) * 32] = __uint_as_float(f2tf(f0));
            dst[(2 * lvl + 1) * 32] = __uint_as_float(f2tf(f1));
        }
    }
}

// ======================= Kernel B: MLP (tiled) =======================
constexpr int SA_STR = 33;            // sA[k][row]
constexpr int SC_STR = 68;            // sC[row][k], 272B rows
constexpr int SW2_STR = 68;           // W2T[n][k]
constexpr int WBLK   = 32 * SC_STR;
constexpr int TILES  = 4;             // 32-point tiles per warp
constexpr int CTA_PTS = 128 * TILES;  // 512 points per CTA
constexpr int SMEM_BYTES = (4 * WBLK + 64 * SW2_STR) * 4;   // 52224

__global__ __launch_bounds__(128, 4) void ngp_mlp(
    const float* __restrict__ W1,
    const float* __restrict__ W2,
    const float* __restrict__ W3,
    float* __restrict__ out,
    int n)
{
    extern __shared__ float sm[];
    float* sW2T = sm + 4 * WBLK;        // [64 n][68] tf32, transposed

    const int t    = threadIdx.x;
    const int lane = t & 31;
    const int warp = t >> 5;
    const int g    = lane >> 2;
    const int q    = lane & 3;

    float* sW = sm + warp * WBLK;       // sA: [k][row] str 33; sC: [row][k] str 68

    // ---- stage W2 transposed, ONCE per CTA ----
    for (int i = t; i < 64 * 64; i += 128) {
        int k = i >> 6, c = i & 63;
        sW2T[c * SW2_STR + k] = __uint_as_float(f2tf(W2[i]));
    }
    __syncthreads();

    // hoisted ldmatrix bases (lane-dependent only)
    const uint32_t sw_u32   = (uint32_t)__cvta_generic_to_shared(sW);
    const uint32_t sw2t_u32 = (uint32_t)__cvta_generic_to_shared(sW2T);
    const int m_ = lane >> 3;
    const int r8 = lane & 7;
    const uint32_t aaddr0 = sw_u32 + ((r8 + 8 * (m_ & 1)) * SC_STR + 4 * (m_ >> 1)) * 4;
    const uint32_t aaddr1 = aaddr0 + 16 * SC_STR * 4;
    const uint32_t baddr  = sw2t_u32 + (((m_ >> 1) * 8 + r8) * SW2_STR + 4 * (m_ & 1)) * 4;

    const int warp_base = blockIdx.x * CTA_PTS + warp * (32 * TILES);

    for (int tt = 0; tt < TILES; tt++) {
        const int pbase = warp_base + tt * 32;

        // ---- feat copy: this warp's tile (1024 contiguous floats) -> sA ----
        {
            const float4* src = (const float4*)(g_feat + ((size_t)(pbase >> 5) << 10));
#pragma unroll
            for (int j = 0; j < 8; j++) {
                int i4 = j * 32 + lane;
                float4 v = __ldg(src + i4);
                int k = i4 >> 3;
                int r = (i4 & 7) * 4;
                float* d = sW + k * SA_STR + r;
                d[0] = v.x; d[1] = v.y; d[2] = v.z; d[3] = v.w;
            }
        }
        __syncwarp();

        // ---- GEMM1: C1[32x64] = A[32x32] @ W1[32x64] ----
        float acc[2][8][4];
#pragma unroll
        for (int mt = 0; mt < 2; mt++)
#pragma unroll
            for (int nt = 0; nt < 8; nt++)
#pragma unroll
                for (int r = 0; r < 4; r++) acc[mt][nt][r] = 0.f;

#pragma unroll
        for (int k0 = 0; k0 < 32; k0 += 8) {
            uint32_t a[2][4];
#pragma unroll
            for (int mt = 0; mt < 2; mt++) {
                int lr = mt * 16 + g;
                a[mt][0] = __float_as_uint(sW[(k0 + q) * SA_STR + lr]);
                a[mt][1] = __float_as_uint(sW[(k0 + q) * SA_STR + lr + 8]);
                a[mt][2] = __float_as_uint(sW[(k0 + q + 4) * SA_STR + lr]);
                a[mt][3] = __float_as_uint(sW[(k0 + q + 4) * SA_STR + lr + 8]);
            }
#pragma unroll
            for (int nt = 0; nt < 8; nt++) {
                uint32_t b[2];
                b[0] = f2tf(__ldg(&W1[(k0 + q)     * 64 + nt * 8 + g]));
                b[1] = f2tf(__ldg(&W1[(k0 + q + 4) * 64 + nt * 8 + g]));
                mma8(acc[0][nt], a[0], b);
                mma8(acc[1][nt], a[1], b);
            }
        }
        __syncwarp();

        // ---- ReLU + store C1 into sC [row][k] ----
#pragma unroll
        for (int mt = 0; mt < 2; mt++) {
            int lr = mt * 16 + g;
#pragma unroll
            for (int nt = 0; nt < 8; nt++) {
                int c = nt * 8 + 2 * q;
                sW[lr * SC_STR + c]           = __uint_as_float(f2tf(fmaxf(acc[mt][nt][0], 0.f)));
                sW[lr * SC_STR + c + 1]       = __uint_as_float(f2tf(fmaxf(acc[mt][nt][1], 0.f)));
                sW[(lr + 8) * SC_STR + c]     = __uint_as_float(f2tf(fmaxf(acc[mt][nt][2], 0.f)));
                sW[(lr + 8) * SC_STR + c + 1] = __uint_as_float(f2tf(fmaxf(acc[mt][nt][3], 0.f)));
            }
        }
        __syncwarp();

        // ---- GEMM2 via ldmatrix ----
        float acc2[2][8][4];
#pragma unroll
        for (int mt = 0; mt < 2; mt++)
#pragma unroll
            for (int nt = 0; nt < 8; nt++)
#pragma unroll
                for (int r = 0; r < 4; r++) acc2[mt][nt][r] = 0.f;

#pragma unroll
        for (int k0 = 0; k0 < 64; k0 += 8) {
            uint32_t a0r[4], a1r[4];
            ldsm4(a0r, aaddr0 + k0 * 4);
            ldsm4(a1r, aaddr1 + k0 * 4);
#pragma unroll
            for (int nt0 = 0; nt0 < 8; nt0 += 2) {
                uint32_t br[4];
                ldsm4(br, baddr + (nt0 * 8 * SW2_STR + k0) * 4);
                mma8(acc2[0][nt0],     a0r, &br[0]);
                mma8(acc2[1][nt0],     a1r, &br[0]);
                mma8(acc2[0][nt0 + 1], a0r, &br[2]);
                mma8(acc2[1][nt0 + 1], a1r, &br[2]);
            }
        }

        // ---- epilogue: ReLU + layer3 + quad reduce ----
        float o[2][2][3];
#pragma unroll
        for (int mt = 0; mt < 2; mt++)
#pragma unroll
            for (int h = 0; h < 2; h++)
#pragma unroll
                for (int j = 0; j < 3; j++) o[mt][h][j] = 0.f;

#pragma unroll
        for (int nt = 0; nt < 8; nt++) {
            int c0 = nt * 8 + 2 * q;
            float w30[3], w31[3];
#pragma unroll
            for (int j = 0; j < 3; j++) {
                w30[j] = __ldg(&W3[c0 * 3 + j]);
                w31[j] = __ldg(&W3[(c0 + 1) * 3 + j]);
            }
#pragma unroll
            for (int mt = 0; mt < 2; mt++) {
                float v0 = fmaxf(acc2[mt][nt][0], 0.f);
                float v1 = fmaxf(acc2[mt][nt][1], 0.f);
                float v2 = fmaxf(acc2[mt][nt][2], 0.f);
                float v3 = fmaxf(acc2[mt][nt][3], 0.f);
#pragma unroll
                for (int j = 0; j < 3; j++) {
                    o[mt][0][j] += v0 * w30[j] + v1 * w31[j];
                    o[mt][1][j] += v2 * w30[j] + v3 * w31[j];
                }
            }
        }

#pragma unroll
        for (int mt = 0; mt < 2; mt++)
#pragma unroll
            for (int h = 0; h < 2; h++)
#pragma unroll
                for (int j = 0; j < 3; j++) {
                    float v = o[mt][h][j];
                    v += __shfl_xor_sync(0xffffffffu, v, 1);
                    v += __shfl_xor_sync(0xffffffffu, v, 2);
                    o[mt][h][j] = v;
                }

        if (q < 3) {
            int j = q;
#pragma unroll
            for (int mt = 0; mt < 2; mt++)
#pragma unroll
                for (int h = 0; h < 2; h++) {
                    int row = pbase + mt * 16 + g + h * 8;
                    if (row < n) out[row * 3 + j] = o[mt][h][j];
                }
        }
        __syncwarp();   // sC reads done before next tile's feat copy
    }
}

extern "C" void kernel_launch(void* const* d_in, const int* in_sizes, int n_in,
                              void* d_out, int out_size) {
    const float* pos   = (const float*)d_in[0];
    const float* table = (const float*)d_in[1];
    const float* W1    = (const float*)d_in[2];
    const float* W2    = (const float*)d_in[3];
    const float* W3    = (const float*)d_in[4];
    float* out = (float*)d_out;
    int n = in_sizes[0] / 2;

    static bool attr_set = false;
    if (!attr_set) {
        cudaFuncSetAttribute(ngp_mlp, cudaFuncAttributeMaxDynamicSharedMemorySize,
                             SMEM_BYTES);
        attr_set = true;
    }

    ngp_encode<<<(n + 255) / 256, 256>>>(pos, table, n);
    ngp_mlp<<<(n + CTA_PTS - 1) / CTA_PTS, 128, SMEM_BYTES>>>(W1, W2, W3, out, n);
}